// round 2
// baseline (speedup 1.0000x reference)
#include <cuda_runtime.h>
#include <math.h>

#define EPSBN 1e-5f
#define BSZ 8
#define CIN 256
#define C2 128
#define HW 4096
#define HW4 1024

// ---------------- scratch (device globals; no runtime allocation) ----------------
__device__ float g_x1[(size_t)BSZ * HW * C2];      // conv1 out, NCHW flat == x1 [4096,128] rm
__device__ float g_c2[(size_t)BSZ * C2 * HW];      // conv2 out (pre-pool), NCHW
__device__ float g_p23[(size_t)BSZ * C2 * HW4];    // pooled: x2 [128,1024] rm == x3 [1024,128] rm
__device__ float g_S[(size_t)BSZ * HW * HW4];      // logits [4096,1024] per batch
__device__ float g_rmax[BSZ * HW];
__device__ float g_rsum[BSZ * HW];
__device__ float g_O[(size_t)BSZ * HW * C2];       // attention out [4096,128] rm == NCHW [128,4096]

// ---------------- packed f32x2 helpers (FFMA2 path, sm_100+) ----------------
__device__ __forceinline__ unsigned long long pack2(float lo, float hi) {
    unsigned long long r;
    asm("mov.b64 %0, {%1, %2};" : "=l"(r) : "f"(lo), "f"(hi));
    return r;
}
__device__ __forceinline__ void ffma2(unsigned long long& d,
                                      unsigned long long a,
                                      unsigned long long b) {
    asm("fma.rn.f32x2 %0, %1, %2, %0;" : "+l"(d) : "l"(a), "l"(b));
}
__device__ __forceinline__ float2 unpack2(unsigned long long v) {
    float2 f;
    asm("mov.b64 {%0, %1}, %2;" : "=f"(f.x), "=f"(f.y) : "l"(v));
    return f;
}

// ---------------- generic tiled GEMM: C = f(A[M,K] rm) * B[K,N] rm ----------------
// MODE 0: plain store
// MODE 1: BN+ReLU epilogue (per-row channel params)
// MODE 2: BN+ReLU + residual add
// MODE 3: A-transform exp(a - rowmax[m]); epilogue scale by 1/rowsum[m]
struct GemmArgs {
    const float* A; const float* B; float* C;
    int M, N, K;
    long long sAb, sBb, sCb;            // per-batch strides (elements)
    const float* bias; const float* g; const float* beta;
    const float* mean; const float* var;
    const float* res; long long sResB;
    const float* rowmax; const float* rowsum;
};

template <int MODE>
__global__ __launch_bounds__(256, 2) void gemm_k(GemmArgs ga) {
    __shared__ float As[16][128];
    __shared__ float Bs[16][128];

    const int bz = blockIdx.z;
    const float* A = ga.A + (size_t)bz * ga.sAb;
    const float* Bp = ga.B + (size_t)bz * ga.sBb;
    float* C = ga.C + (size_t)bz * ga.sCb;

    const int mBase = blockIdx.y * 128;
    const int nBase = blockIdx.x * 128;
    const int tid = threadIdx.x;
    const int tx = tid & 15, ty = tid >> 4;
    const int N = ga.N, K = ga.K;

    const float* rmax = nullptr;
    if (MODE == 3) rmax = ga.rowmax + (size_t)bz * ga.M;

    // acc2[i][j] holds output (row ty*8+i, cols nBase+tx*8+2j, +2j+1) as f32x2
    unsigned long long acc2[8][4];
    const unsigned long long zz = pack2(0.f, 0.f);
#pragma unroll
    for (int i = 0; i < 8; i++)
#pragma unroll
        for (int j = 0; j < 4; j++) acc2[i][j] = zz;

    for (int k0 = 0; k0 < K; k0 += 16) {
        // A tile: 128 rows x 16 k, row-major stride K. 512 float4, 2 per thread.
#pragma unroll
        for (int i = 0; i < 2; i++) {
            int idx = tid + i * 256;
            int row = idx >> 2;
            int k4 = (idx & 3) << 2;
            float4 v = *(const float4*)(A + (size_t)(mBase + row) * K + k0 + k4);
            if (MODE == 3) {
                float rm = rmax[mBase + row];
                v.x = __expf(v.x - rm); v.y = __expf(v.y - rm);
                v.z = __expf(v.z - rm); v.w = __expf(v.w - rm);
            }
            As[k4 + 0][row] = v.x; As[k4 + 1][row] = v.y;
            As[k4 + 2][row] = v.z; As[k4 + 3][row] = v.w;
        }
        // B tile: 16 k-rows x 128 n, row-major stride N.
#pragma unroll
        for (int i = 0; i < 2; i++) {
            int idx = tid + i * 256;
            int kr = idx >> 5;
            int n4 = (idx & 31) << 2;
            *(float4*)&Bs[kr][n4] =
                *(const float4*)(Bp + (size_t)(k0 + kr) * N + nBase + n4);
        }
        __syncthreads();
#pragma unroll
        for (int k = 0; k < 16; k++) {
            float4 a0 = *(float4*)&As[k][ty * 8];
            float4 a1 = *(float4*)&As[k][ty * 8 + 4];
            float4 b0 = *(float4*)&Bs[k][tx * 8];
            float4 b1 = *(float4*)&Bs[k][tx * 8 + 4];
            unsigned long long bp[4];
            bp[0] = pack2(b0.x, b0.y); bp[1] = pack2(b0.z, b0.w);
            bp[2] = pack2(b1.x, b1.y); bp[3] = pack2(b1.z, b1.w);
            float ar[8] = {a0.x, a0.y, a0.z, a0.w, a1.x, a1.y, a1.z, a1.w};
#pragma unroll
            for (int i = 0; i < 8; i++) {
                unsigned long long ad = pack2(ar[i], ar[i]);
#pragma unroll
                for (int j = 0; j < 4; j++) ffma2(acc2[i][j], ad, bp[j]);
            }
        }
        __syncthreads();
    }

    // epilogue
#pragma unroll
    for (int i = 0; i < 8; i++) {
        int m = mBase + ty * 8 + i;
        float sc = 1.f, sh = 0.f, bi = 0.f, inv = 1.f;
        if (MODE == 1 || MODE == 2) {
            sc = ga.g[m] * rsqrtf(ga.var[m] + EPSBN);
            sh = ga.beta[m] - ga.mean[m] * sc;
            bi = ga.bias[m];
        }
        if (MODE == 3) inv = 1.0f / ga.rowsum[(size_t)bz * ga.M + m];
#pragma unroll
        for (int j = 0; j < 2; j++) {
            float2 p0 = unpack2(acc2[i][j * 2 + 0]);
            float2 p1 = unpack2(acc2[i][j * 2 + 1]);
            float vals[4] = {p0.x, p0.y, p1.x, p1.y};
            float4 v;
            float* pv = &v.x;
#pragma unroll
            for (int c = 0; c < 4; c++) {
                int n = nBase + tx * 8 + j * 4 + c;
                float val = vals[c];
                if (MODE == 1 || MODE == 2) {
                    val = (val + bi) * sc + sh;
                    val = fmaxf(val, 0.f);
                }
                if (MODE == 2)
                    val += ga.res[(size_t)bz * ga.sResB + (size_t)m * N + n];
                if (MODE == 3) val *= inv;
                pv[c] = val;
            }
            *(float4*)(C + (size_t)m * N + nBase + tx * 8 + j * 4) = v;
        }
    }
}

// ---------------- maxpool 3x3 s2 p1 : [B*C2,64,64] -> [B*C2,32,32] ----------------
__global__ __launch_bounds__(256) void maxpool_k(const float* __restrict__ in,
                                                 float* __restrict__ out) {
    int idx = blockIdx.x * blockDim.x + threadIdx.x;
    if (idx >= BSZ * C2 * 1024) return;
    int ow = idx & 31, oh = (idx >> 5) & 31, ch = idx >> 10;
    const float* p = in + (size_t)ch * 4096;
    int h0 = oh * 2 - 1, w0 = ow * 2 - 1;
    float m = -INFINITY;
#pragma unroll
    for (int dh = 0; dh < 3; dh++) {
        int h = h0 + dh;
        if (h < 0 || h >= 64) continue;
#pragma unroll
        for (int dw = 0; dw < 3; dw++) {
            int w = w0 + dw;
            if (w < 0 || w >= 64) continue;
            m = fmaxf(m, p[h * 64 + w]);
        }
    }
    out[idx] = m;
}

// ---------------- per-row max & sum(exp(x-max)) over 1024-wide rows ----------------
__global__ __launch_bounds__(256) void stats_k(const float* __restrict__ S,
                                               float* __restrict__ rmax,
                                               float* __restrict__ rsum) {
    int warp = (blockIdx.x * blockDim.x + threadIdx.x) >> 5;
    int lane = threadIdx.x & 31;
    if (warp >= BSZ * HW) return;
    const float* row = S + (size_t)warp * 1024;
    float v[32];
    float mx = -INFINITY;
#pragma unroll
    for (int i = 0; i < 32; i++) {
        v[i] = row[lane + i * 32];
        mx = fmaxf(mx, v[i]);
    }
#pragma unroll
    for (int o = 16; o > 0; o >>= 1)
        mx = fmaxf(mx, __shfl_xor_sync(0xffffffffu, mx, o));
    float s = 0.f;
#pragma unroll
    for (int i = 0; i < 32; i++) s += __expf(v[i] - mx);
#pragma unroll
    for (int o = 16; o > 0; o >>= 1)
        s += __shfl_xor_sync(0xffffffffu, s, o);
    if (lane == 0) {
        rmax[warp] = mx;
        rsum[warp] = s;
    }
}

// ---------------- launcher ----------------
extern "C" void kernel_launch(void* const* d_in, const int* in_sizes, int n_in,
                              void* d_out, int out_size) {
    const float* a       = (const float*)d_in[0];
    const float* conv1_w = (const float*)d_in[1];
    const float* conv1_b = (const float*)d_in[2];
    const float* bn1_g   = (const float*)d_in[3];
    const float* bn1_b   = (const float*)d_in[4];
    const float* bn1_m   = (const float*)d_in[5];
    const float* bn1_v   = (const float*)d_in[6];
    const float* conv2_w = (const float*)d_in[7];
    const float* conv2_b = (const float*)d_in[8];
    const float* bn2_g   = (const float*)d_in[9];
    const float* bn2_b   = (const float*)d_in[10];
    const float* bn2_m   = (const float*)d_in[11];
    const float* bn2_v   = (const float*)d_in[12];
    const float* conv3_w = (const float*)d_in[13];
    const float* conv3_b = (const float*)d_in[14];
    const float* bn3_g   = (const float*)d_in[15];
    const float* bn3_b   = (const float*)d_in[16];
    const float* bn3_m   = (const float*)d_in[17];
    const float* bn3_v   = (const float*)d_in[18];
    float* out = (float*)d_out;

    float *px1, *pc2, *pp, *pS, *prm, *prs, *pO;
    cudaGetSymbolAddress((void**)&px1, g_x1);
    cudaGetSymbolAddress((void**)&pc2, g_c2);
    cudaGetSymbolAddress((void**)&pp, g_p23);
    cudaGetSymbolAddress((void**)&pS, g_S);
    cudaGetSymbolAddress((void**)&prm, g_rmax);
    cudaGetSymbolAddress((void**)&prs, g_rsum);
    cudaGetSymbolAddress((void**)&pO, g_O);

    GemmArgs ga;

    // K1: x1 = BN(ReLU(conv1(a)))  ->  [B,128,4096] NCHW flat
    ga = {};
    ga.A = conv1_w; ga.B = a; ga.C = px1;
    ga.M = C2; ga.N = HW; ga.K = CIN;
    ga.sAb = 0; ga.sBb = (long long)CIN * HW; ga.sCb = (long long)C2 * HW;
    ga.bias = conv1_b; ga.g = bn1_g; ga.beta = bn1_b; ga.mean = bn1_m; ga.var = bn1_v;
    gemm_k<1><<<dim3(HW / 128, C2 / 128, BSZ), 256>>>(ga);

    // K2: conv2 branch (pre-pool)
    ga = {};
    ga.A = conv2_w; ga.B = a; ga.C = pc2;
    ga.M = C2; ga.N = HW; ga.K = CIN;
    ga.sAb = 0; ga.sBb = (long long)CIN * HW; ga.sCb = (long long)C2 * HW;
    ga.bias = conv2_b; ga.g = bn2_g; ga.beta = bn2_b; ga.mean = bn2_m; ga.var = bn2_v;
    gemm_k<1><<<dim3(HW / 128, C2 / 128, BSZ), 256>>>(ga);

    // K3: maxpool -> pooled buffer (x2/x3 views)
    maxpool_k<<<(BSZ * C2 * 1024 + 255) / 256, 256>>>(pc2, pp);

    // K4: S = x1 @ x2   (M=4096, N=1024, K=128)
    ga = {};
    ga.A = px1; ga.B = pp; ga.C = pS;
    ga.M = HW; ga.N = HW4; ga.K = C2;
    ga.sAb = (long long)HW * C2; ga.sBb = (long long)C2 * HW4;
    ga.sCb = (long long)HW * HW4;
    gemm_k<0><<<dim3(HW4 / 128, HW / 128, BSZ), 256>>>(ga);

    // K5: row softmax stats
    stats_k<<<(BSZ * HW) / 8, 256>>>(pS, prm, prs);

    // K6: O = softmax(S) @ x3   (M=4096, N=128, K=1024)
    ga = {};
    ga.A = pS; ga.B = pp; ga.C = pO;
    ga.M = HW; ga.N = C2; ga.K = HW4;
    ga.sAb = (long long)HW * HW4; ga.sBb = (long long)C2 * HW4;
    ga.sCb = (long long)HW * C2;
    ga.rowmax = prm; ga.rowsum = prs;
    gemm_k<3><<<dim3(C2 / 128, HW / 128, BSZ), 256>>>(ga);

    // K7: out = ReLU(BN(conv3(O))) + a   (M=256, N=4096, K=128)
    ga = {};
    ga.A = conv3_w; ga.B = pO; ga.C = out;
    ga.M = CIN; ga.N = HW; ga.K = C2;
    ga.sAb = 0; ga.sBb = (long long)C2 * HW; ga.sCb = (long long)CIN * HW;
    ga.bias = conv3_b; ga.g = bn3_g; ga.beta = bn3_b; ga.mean = bn3_m; ga.var = bn3_v;
    ga.res = a; ga.sResB = (long long)CIN * HW;
    gemm_k<2><<<dim3(HW / 128, CIN / 128, BSZ), 256>>>(ga);
}

// round 3
// speedup vs baseline: 2.2229x; 2.2229x over previous
#include <cuda_runtime.h>
#include <math.h>
#include <stdint.h>

#define EPSBN 1e-5f
#define BSZ 8
#define CIN 256
#define C2 128
#define HW 4096
#define HW4 1024

// ---------------- scratch (device globals; no runtime allocation) ----------------
__device__ float g_x1[(size_t)BSZ * HW * C2];      // conv1 out NCHW flat == x1 [4096,128] rm
__device__ float g_c2[(size_t)BSZ * C2 * HW];      // conv2 out (pre-pool) NCHW
__device__ float g_p23[(size_t)BSZ * C2 * HW4];    // pooled: x2 [128,1024] rm == x3 [1024,128] rm
__device__ float g_S[(size_t)BSZ * HW * HW4];      // logits [4096,1024] per batch
__device__ float g_rmax[BSZ * HW];
__device__ float g_rsum[BSZ * HW];
__device__ float g_O[(size_t)BSZ * HW * C2];       // attn out [4096,128] rm == NCHW [128,4096]

// ---------------- helpers ----------------
__device__ __forceinline__ uint32_t f2tf32(float f) {
    uint32_t u;
    asm("cvt.rna.tf32.f32 %0, %1;" : "=r"(u) : "f"(f));
    return u;
}

__device__ __forceinline__ void mma_tf32(float d[4], uint32_t a0, uint32_t a1,
                                         uint32_t a2, uint32_t a3,
                                         uint32_t b0, uint32_t b1) {
    asm volatile(
        "mma.sync.aligned.m16n8k8.row.col.f32.tf32.tf32.f32 "
        "{%0,%1,%2,%3},{%4,%5,%6,%7},{%8,%9},{%0,%1,%2,%3};"
        : "+f"(d[0]), "+f"(d[1]), "+f"(d[2]), "+f"(d[3])
        : "r"(a0), "r"(a1), "r"(a2), "r"(a3), "r"(b0), "r"(b1));
}

// ---------------- tensor-core tiled GEMM: C = f(A[M,K] rm) * B[K,N] rm ----------
// MODE 0: plain store
// MODE 1: BN+ReLU epilogue (per-M-row channel params)
// MODE 2: BN+ReLU + residual add
// MODE 3: A-transform exp(a - rowmax[m]); epilogue scale by 1/rowsum[m]
struct GemmArgs {
    const float* A; const float* B; float* C;
    int M, N, K;
    long long sAb, sBb, sCb;
    const float* bias; const float* g; const float* beta;
    const float* mean; const float* var;
    const float* res; long long sResB;
    const float* rowmax; const float* rowsum;
};

#define SMS 136  // smem row stride (floats): (8k + n) covers 32 distinct banks

template <int MODE>
__global__ __launch_bounds__(256, 2) void gemm_mma(GemmArgs ga) {
    __shared__ uint32_t As[16][SMS];   // [k][m], tf32 bits
    __shared__ uint32_t Bs[16][SMS];   // [k][n], tf32 bits

    const int bz = blockIdx.z;
    const float* A = ga.A + (size_t)bz * ga.sAb;
    const float* Bp = ga.B + (size_t)bz * ga.sBb;
    float* C = ga.C + (size_t)bz * ga.sCb;

    const int mBase = blockIdx.y * 128;
    const int nBase = blockIdx.x * 128;
    const int tid = threadIdx.x;
    const int lane = tid & 31;
    const int warp = tid >> 5;
    const int wm = warp >> 2;          // 0..1 -> 64 rows each
    const int wn = warp & 3;           // 0..3 -> 32 cols each
    const int mW = wm * 64;            // within block tile
    const int nW = wn * 32;
    const int gp = lane >> 2;          // 0..7
    const int lq = lane & 3;           // 0..3
    const int N = ga.N, K = ga.K;

    const float* rmax = nullptr;
    if (MODE == 3) rmax = ga.rowmax + (size_t)bz * ga.M;

    float acc[4][4][4];
#pragma unroll
    for (int i = 0; i < 4; i++)
#pragma unroll
        for (int j = 0; j < 4; j++)
#pragma unroll
            for (int r = 0; r < 4; r++) acc[i][j][r] = 0.f;

    for (int k0 = 0; k0 < K; k0 += 16) {
        // A tile: 128 rows x 16 k (row-major global, stride K) -> As[k][m]
#pragma unroll
        for (int it = 0; it < 2; it++) {
            int idx = tid + it * 256;
            int row = idx >> 2;
            int k4 = (idx & 3) << 2;
            float4 v = *(const float4*)(A + (size_t)(mBase + row) * K + k0 + k4);
            if (MODE == 3) {
                float rm = rmax[mBase + row];
                v.x = __expf(v.x - rm); v.y = __expf(v.y - rm);
                v.z = __expf(v.z - rm); v.w = __expf(v.w - rm);
            }
            As[k4 + 0][row] = f2tf32(v.x);
            As[k4 + 1][row] = f2tf32(v.y);
            As[k4 + 2][row] = f2tf32(v.z);
            As[k4 + 3][row] = f2tf32(v.w);
        }
        // B tile: 16 k-rows x 128 n (row-major global, stride N) -> Bs[k][n]
#pragma unroll
        for (int it = 0; it < 2; it++) {
            int idx = tid + it * 256;
            int kr = idx >> 5;
            int n4 = (idx & 31) << 2;
            float4 v = *(const float4*)(Bp + (size_t)(k0 + kr) * N + nBase + n4);
            uint4 u;
            u.x = f2tf32(v.x); u.y = f2tf32(v.y);
            u.z = f2tf32(v.z); u.w = f2tf32(v.w);
            *(uint4*)&Bs[kr][n4] = u;
        }
        __syncthreads();

#pragma unroll
        for (int ks = 0; ks < 16; ks += 8) {
            uint32_t b0[4], b1[4];
#pragma unroll
            for (int j = 0; j < 4; j++) {
                b0[j] = Bs[ks + lq][nW + j * 8 + gp];
                b1[j] = Bs[ks + lq + 4][nW + j * 8 + gp];
            }
#pragma unroll
            for (int i = 0; i < 4; i++) {
                int m0 = mW + i * 16 + gp;
                uint32_t a0 = As[ks + lq][m0];
                uint32_t a1 = As[ks + lq][m0 + 8];
                uint32_t a2 = As[ks + lq + 4][m0];
                uint32_t a3 = As[ks + lq + 4][m0 + 8];
#pragma unroll
                for (int j = 0; j < 4; j++)
                    mma_tf32(acc[i][j], a0, a1, a2, a3, b0[j], b1[j]);
            }
        }
        __syncthreads();
    }

    // epilogue: per (i): rows r0 = mBase+mW+i*16+gp, r1 = r0+8
#pragma unroll
    for (int i = 0; i < 4; i++) {
        int r0 = mBase + mW + i * 16 + gp;
        int r1 = r0 + 8;
        float sc0 = 1.f, sh0 = 0.f, bi0 = 0.f, iv0 = 1.f;
        float sc1 = 1.f, sh1 = 0.f, bi1 = 0.f, iv1 = 1.f;
        if (MODE == 1 || MODE == 2) {
            sc0 = ga.g[r0] * rsqrtf(ga.var[r0] + EPSBN);
            sh0 = ga.beta[r0] - ga.mean[r0] * sc0;
            bi0 = ga.bias[r0];
            sc1 = ga.g[r1] * rsqrtf(ga.var[r1] + EPSBN);
            sh1 = ga.beta[r1] - ga.mean[r1] * sc1;
            bi1 = ga.bias[r1];
        }
        if (MODE == 3) {
            iv0 = 1.0f / ga.rowsum[(size_t)bz * ga.M + r0];
            iv1 = 1.0f / ga.rowsum[(size_t)bz * ga.M + r1];
        }
#pragma unroll
        for (int j = 0; j < 4; j++) {
            int c = nBase + nW + j * 8 + 2 * lq;
            float v0 = acc[i][j][0], v1 = acc[i][j][1];
            float v2 = acc[i][j][2], v3 = acc[i][j][3];
            if (MODE == 1 || MODE == 2) {
                v0 = fmaxf((v0 + bi0) * sc0 + sh0, 0.f);
                v1 = fmaxf((v1 + bi0) * sc0 + sh0, 0.f);
                v2 = fmaxf((v2 + bi1) * sc1 + sh1, 0.f);
                v3 = fmaxf((v3 + bi1) * sc1 + sh1, 0.f);
            }
            if (MODE == 2) {
                const float* rp = ga.res + (size_t)bz * ga.sResB;
                float2 q0 = *(const float2*)(rp + (size_t)r0 * N + c);
                float2 q1 = *(const float2*)(rp + (size_t)r1 * N + c);
                v0 += q0.x; v1 += q0.y; v2 += q1.x; v3 += q1.y;
            }
            if (MODE == 3) { v0 *= iv0; v1 *= iv0; v2 *= iv1; v3 *= iv1; }
            *(float2*)(C + (size_t)r0 * N + c) = make_float2(v0, v1);
            *(float2*)(C + (size_t)r1 * N + c) = make_float2(v2, v3);
        }
    }
}

// ---------------- maxpool 3x3 s2 p1 : [B*C2,64,64] -> [B*C2,32,32] ----------------
__global__ __launch_bounds__(256) void maxpool_k(const float* __restrict__ in,
                                                 float* __restrict__ out) {
    int idx = blockIdx.x * blockDim.x + threadIdx.x;
    if (idx >= BSZ * C2 * 1024) return;
    int ow = idx & 31, oh = (idx >> 5) & 31, ch = idx >> 10;
    const float* p = in + (size_t)ch * 4096;
    int h0 = oh * 2 - 1, w0 = ow * 2 - 1;
    float m = -INFINITY;
#pragma unroll
    for (int dh = 0; dh < 3; dh++) {
        int h = h0 + dh;
        if (h < 0 || h >= 64) continue;
#pragma unroll
        for (int dw = 0; dw < 3; dw++) {
            int w = w0 + dw;
            if (w < 0 || w >= 64) continue;
            m = fmaxf(m, p[h * 64 + w]);
        }
    }
    out[idx] = m;
}

// ---------------- per-row max & sum(exp(x-max)) over 1024-wide rows ----------------
__global__ __launch_bounds__(256) void stats_k(const float* __restrict__ S,
                                               float* __restrict__ rmax,
                                               float* __restrict__ rsum) {
    int warp = (blockIdx.x * blockDim.x + threadIdx.x) >> 5;
    int lane = threadIdx.x & 31;
    if (warp >= BSZ * HW) return;
    const float* row = S + (size_t)warp * 1024;
    float v[32];
    float mx = -INFINITY;
#pragma unroll
    for (int i = 0; i < 32; i++) {
        v[i] = row[lane + i * 32];
        mx = fmaxf(mx, v[i]);
    }
#pragma unroll
    for (int o = 16; o > 0; o >>= 1)
        mx = fmaxf(mx, __shfl_xor_sync(0xffffffffu, mx, o));
    float s = 0.f;
#pragma unroll
    for (int i = 0; i < 32; i++) s += __expf(v[i] - mx);
#pragma unroll
    for (int o = 16; o > 0; o >>= 1)
        s += __shfl_xor_sync(0xffffffffu, s, o);
    if (lane == 0) {
        rmax[warp] = mx;
        rsum[warp] = s;
    }
}

// ---------------- launcher ----------------
extern "C" void kernel_launch(void* const* d_in, const int* in_sizes, int n_in,
                              void* d_out, int out_size) {
    const float* a       = (const float*)d_in[0];
    const float* conv1_w = (const float*)d_in[1];
    const float* conv1_b = (const float*)d_in[2];
    const float* bn1_g   = (const float*)d_in[3];
    const float* bn1_b   = (const float*)d_in[4];
    const float* bn1_m   = (const float*)d_in[5];
    const float* bn1_v   = (const float*)d_in[6];
    const float* conv2_w = (const float*)d_in[7];
    const float* conv2_b = (const float*)d_in[8];
    const float* bn2_g   = (const float*)d_in[9];
    const float* bn2_b   = (const float*)d_in[10];
    const float* bn2_m   = (const float*)d_in[11];
    const float* bn2_v   = (const float*)d_in[12];
    const float* conv3_w = (const float*)d_in[13];
    const float* conv3_b = (const float*)d_in[14];
    const float* bn3_g   = (const float*)d_in[15];
    const float* bn3_b   = (const float*)d_in[16];
    const float* bn3_m   = (const float*)d_in[17];
    const float* bn3_v   = (const float*)d_in[18];
    float* out = (float*)d_out;

    float *px1, *pc2, *pp, *pS, *prm, *prs, *pO;
    cudaGetSymbolAddress((void**)&px1, g_x1);
    cudaGetSymbolAddress((void**)&pc2, g_c2);
    cudaGetSymbolAddress((void**)&pp, g_p23);
    cudaGetSymbolAddress((void**)&pS, g_S);
    cudaGetSymbolAddress((void**)&prm, g_rmax);
    cudaGetSymbolAddress((void**)&prs, g_rsum);
    cudaGetSymbolAddress((void**)&pO, g_O);

    GemmArgs ga;

    // K1: x1 = ReLU(BN(conv1(a)))  ->  [B,128,4096] NCHW flat
    ga = {};
    ga.A = conv1_w; ga.B = a; ga.C = px1;
    ga.M = C2; ga.N = HW; ga.K = CIN;
    ga.sAb = 0; ga.sBb = (long long)CIN * HW; ga.sCb = (long long)C2 * HW;
    ga.bias = conv1_b; ga.g = bn1_g; ga.beta = bn1_b; ga.mean = bn1_m; ga.var = bn1_v;
    gemm_mma<1><<<dim3(HW / 128, C2 / 128, BSZ), 256>>>(ga);

    // K2: conv2 branch (pre-pool)
    ga = {};
    ga.A = conv2_w; ga.B = a; ga.C = pc2;
    ga.M = C2; ga.N = HW; ga.K = CIN;
    ga.sAb = 0; ga.sBb = (long long)CIN * HW; ga.sCb = (long long)C2 * HW;
    ga.bias = conv2_b; ga.g = bn2_g; ga.beta = bn2_b; ga.mean = bn2_m; ga.var = bn2_v;
    gemm_mma<1><<<dim3(HW / 128, C2 / 128, BSZ), 256>>>(ga);

    // K3: maxpool -> pooled (x2/x3 views)
    maxpool_k<<<(BSZ * C2 * 1024 + 255) / 256, 256>>>(pc2, pp);

    // K4: S = x1 @ x2   (M=4096, N=1024, K=128)
    ga = {};
    ga.A = px1; ga.B = pp; ga.C = pS;
    ga.M = HW; ga.N = HW4; ga.K = C2;
    ga.sAb = (long long)HW * C2; ga.sBb = (long long)C2 * HW4;
    ga.sCb = (long long)HW * HW4;
    gemm_mma<0><<<dim3(HW4 / 128, HW / 128, BSZ), 256>>>(ga);

    // K5: row softmax stats
    stats_k<<<(BSZ * HW) / 8, 256>>>(pS, prm, prs);

    // K6: O = softmax(S) @ x3   (M=4096, N=128, K=1024)
    ga = {};
    ga.A = pS; ga.B = pp; ga.C = pO;
    ga.M = HW; ga.N = C2; ga.K = HW4;
    ga.sAb = (long long)HW * HW4; ga.sBb = (long long)C2 * HW4;
    ga.sCb = (long long)HW * C2;
    ga.rowmax = prm; ga.rowsum = prs;
    gemm_mma<3><<<dim3(C2 / 128, HW / 128, BSZ), 256>>>(ga);

    // K7: out = ReLU(BN(conv3(O))) + a   (M=256, N=4096, K=128)
    ga = {};
    ga.A = conv3_w; ga.B = pO; ga.C = out;
    ga.M = CIN; ga.N = HW; ga.K = C2;
    ga.sAb = 0; ga.sBb = (long long)C2 * HW; ga.sCb = (long long)CIN * HW;
    ga.bias = conv3_b; ga.g = bn3_g; ga.beta = bn3_b; ga.mean = bn3_m; ga.var = bn3_v;
    ga.res = a; ga.sResB = (long long)CIN * HW;
    gemm_mma<2><<<dim3(HW / 128, CIN / 128, BSZ), 256>>>(ga);
}

// round 5
// speedup vs baseline: 2.4154x; 1.0866x over previous
#include <cuda_runtime.h>
#include <math.h>
#include <stdint.h>

#define EPSBN 1e-5f
#define BSZ 8
#define CIN 256
#define C2 128
#define HW 4096
#define HW4 1024

// ---------------- scratch (device globals; no runtime allocation) ----------------
__device__ float g_x1[(size_t)BSZ * HW * C2];      // conv1 out NCHW flat == x1 [4096,128] rm
__device__ float g_c2[(size_t)BSZ * C2 * HW];      // conv2 out (pre-pool) NCHW
__device__ float g_p23[(size_t)BSZ * C2 * HW4];    // pooled: x2 [128,1024] rm == x3 [1024,128] rm
__device__ float g_S[(size_t)BSZ * HW * HW4];      // logits [4096,1024] per batch
__device__ float g_rmax[BSZ * HW];
__device__ float g_rsum[BSZ * HW];
__device__ float g_O[(size_t)BSZ * HW * C2];       // attn out [4096,128] rm == NCHW [128,4096]

// ---------------- helpers ----------------
__device__ __forceinline__ uint32_t f2tf32(float f) {
    uint32_t u;
    asm("cvt.rna.tf32.f32 %0, %1;" : "=r"(u) : "f"(f));
    return u;
}

__device__ __forceinline__ void mma_tf32(float d[4], uint32_t a0, uint32_t a1,
                                         uint32_t a2, uint32_t a3,
                                         uint32_t b0, uint32_t b1) {
    asm volatile(
        "mma.sync.aligned.m16n8k8.row.col.f32.tf32.tf32.f32 "
        "{%0,%1,%2,%3},{%4,%5,%6,%7},{%8,%9},{%0,%1,%2,%3};"
        : "+f"(d[0]), "+f"(d[1]), "+f"(d[2]), "+f"(d[3])
        : "r"(a0), "r"(a1), "r"(a2), "r"(a3), "r"(b0), "r"(b1));
}

// ---------------- tensor-core tiled GEMM: C = f(A[M,K] rm) * B[K,N] rm ----------
// 128x128 CTA tile, 4 warps of 64x64, double-buffered smem (round-3 layout).
// MODE 0: plain store
// MODE 1: BN+ReLU epilogue (per-M-row channel params)
// MODE 2: BN+ReLU + residual add
// MODE 3: A-transform exp(a - rowmax[m]); epilogue scale by 1/rowsum[m]
struct GemmArgs {
    const float* A; const float* B; float* C;
    int M, N, K;
    long long sAb, sBb, sCb;
    const float* bias; const float* g; const float* beta;
    const float* mean; const float* var;
    const float* res; long long sResB;
    const float* rowmax; const float* rowsum;
};

#define SMS 136  // smem row stride (floats): k*136+off covers 32 distinct banks

template <int MODE>
__global__ __launch_bounds__(128) void gemm_mma(GemmArgs ga) {
    __shared__ uint32_t As[2][16][SMS];   // [buf][k][m], tf32 bits
    __shared__ uint32_t Bs[2][16][SMS];   // [buf][k][n], tf32 bits

    const int bz = blockIdx.z;
    const float* A = ga.A + (size_t)bz * ga.sAb;
    const float* Bp = ga.B + (size_t)bz * ga.sBb;
    float* C = ga.C + (size_t)bz * ga.sCb;

    const int mBase = blockIdx.y * 128;
    const int nBase = blockIdx.x * 128;
    const int tid = threadIdx.x;
    const int lane = tid & 31;
    const int warp = tid >> 5;         // 0..3
    const int wm = warp >> 1;          // 0..1 (64 rows)
    const int wn = warp & 1;           // 0..1 (64 cols)
    const int gp = lane >> 2;          // 0..7
    const int lq = lane & 3;           // 0..3
    const int N = ga.N, K = ga.K;

    // loader assignments: 4 float4 each for A and B per 16-k chunk (128 threads)
    int aRow[4], aK4[4], bKr[4], bN4[4];
#pragma unroll
    for (int it = 0; it < 4; it++) {
        int idx = tid + it * 128;
        aRow[it] = idx >> 2;
        aK4[it] = (idx & 3) << 2;
        bKr[it] = idx >> 5;
        bN4[it] = (idx & 31) << 2;
    }

    float rmA[4] = {0.f, 0.f, 0.f, 0.f};
    if (MODE == 3) {
        const float* rmax = ga.rowmax + (size_t)bz * ga.M;
#pragma unroll
        for (int it = 0; it < 4; it++) rmA[it] = rmax[mBase + aRow[it]];
    }

    float acc[4][8][4];
#pragma unroll
    for (int i = 0; i < 4; i++)
#pragma unroll
        for (int j = 0; j < 8; j++)
#pragma unroll
            for (int r = 0; r < 4; r++) acc[i][j][r] = 0.f;

    float4 ra[4], rb[4];

    // prologue: load chunk 0 into regs
#pragma unroll
    for (int it = 0; it < 4; it++) {
        ra[it] = *(const float4*)(A + (size_t)(mBase + aRow[it]) * K + aK4[it]);
        rb[it] = *(const float4*)(Bp + (size_t)bKr[it] * N + nBase + bN4[it]);
    }

    int buf = 0;
    for (int k0 = 0; k0 < K; k0 += 16) {
        // regs -> smem[buf]  (A transposed to [k][m]; B to [k][n])
#pragma unroll
        for (int it = 0; it < 4; it++) {
            float v[4] = {ra[it].x, ra[it].y, ra[it].z, ra[it].w};
            if (MODE == 3) {
#pragma unroll
                for (int c = 0; c < 4; c++) v[c] = __expf(v[c] - rmA[it]);
            }
#pragma unroll
            for (int c = 0; c < 4; c++)
                As[buf][aK4[it] + c][aRow[it]] = f2tf32(v[c]);
            uint4 u;
            u.x = f2tf32(rb[it].x); u.y = f2tf32(rb[it].y);
            u.z = f2tf32(rb[it].z); u.w = f2tf32(rb[it].w);
            *(uint4*)&Bs[buf][bKr[it]][bN4[it]] = u;
        }
        __syncthreads();

        // prefetch next chunk into regs
        if (k0 + 16 < K) {
#pragma unroll
            for (int it = 0; it < 4; it++) {
                ra[it] = *(const float4*)(A + (size_t)(mBase + aRow[it]) * K +
                                          (k0 + 16) + aK4[it]);
                rb[it] = *(const float4*)(Bp + (size_t)(k0 + 16 + bKr[it]) * N +
                                          nBase + bN4[it]);
            }
        }

        // compute on smem[buf]: 64x64 warp tile
#pragma unroll
        for (int ks8 = 0; ks8 < 2; ks8++) {
            const int kb = ks8 * 8;
            uint32_t b0[8], b1[8];
#pragma unroll
            for (int j = 0; j < 8; j++) {
                int n = wn * 64 + j * 8 + gp;
                b0[j] = Bs[buf][kb + lq][n];
                b1[j] = Bs[buf][kb + lq + 4][n];
            }
#pragma unroll
            for (int i = 0; i < 4; i++) {
                int m0 = wm * 64 + i * 16 + gp;
                uint32_t a0 = As[buf][kb + lq][m0];
                uint32_t a1 = As[buf][kb + lq][m0 + 8];
                uint32_t a2 = As[buf][kb + lq + 4][m0];
                uint32_t a3 = As[buf][kb + lq + 4][m0 + 8];
#pragma unroll
                for (int j = 0; j < 8; j++)
                    mma_tf32(acc[i][j], a0, a1, a2, a3, b0[j], b1[j]);
            }
        }
        buf ^= 1;
    }

    // epilogue: rows r0 = mBase+wm*64+i*16+gp, r1 = r0+8
#pragma unroll
    for (int i = 0; i < 4; i++) {
        int r0 = mBase + wm * 64 + i * 16 + gp;
        int r1 = r0 + 8;
        float sc0 = 1.f, sh0 = 0.f, bi0 = 0.f, iv0 = 1.f;
        float sc1 = 1.f, sh1 = 0.f, bi1 = 0.f, iv1 = 1.f;
        if (MODE == 1 || MODE == 2) {
            sc0 = ga.g[r0] * rsqrtf(ga.var[r0] + EPSBN);
            sh0 = ga.beta[r0] - ga.mean[r0] * sc0;
            bi0 = ga.bias[r0];
            sc1 = ga.g[r1] * rsqrtf(ga.var[r1] + EPSBN);
            sh1 = ga.beta[r1] - ga.mean[r1] * sc1;
            bi1 = ga.bias[r1];
        }
        if (MODE == 3) {
            iv0 = 1.0f / ga.rowsum[(size_t)bz * ga.M + r0];
            iv1 = 1.0f / ga.rowsum[(size_t)bz * ga.M + r1];
        }
#pragma unroll
        for (int j = 0; j < 8; j++) {
            int c = nBase + wn * 64 + j * 8 + 2 * lq;
            float v0 = acc[i][j][0], v1 = acc[i][j][1];
            float v2 = acc[i][j][2], v3 = acc[i][j][3];
            if (MODE == 1 || MODE == 2) {
                v0 = fmaxf((v0 + bi0) * sc0 + sh0, 0.f);
                v1 = fmaxf((v1 + bi0) * sc0 + sh0, 0.f);
                v2 = fmaxf((v2 + bi1) * sc1 + sh1, 0.f);
                v3 = fmaxf((v3 + bi1) * sc1 + sh1, 0.f);
            }
            if (MODE == 2) {
                const float* rp = ga.res + (size_t)bz * ga.sResB;
                float2 q0 = *(const float2*)(rp + (size_t)r0 * N + c);
                float2 q1 = *(const float2*)(rp + (size_t)r1 * N + c);
                v0 += q0.x; v1 += q0.y; v2 += q1.x; v3 += q1.y;
            }
            if (MODE == 3) { v0 *= iv0; v1 *= iv0; v2 *= iv1; v3 *= iv1; }
            *(float2*)(C + (size_t)r0 * N + c) = make_float2(v0, v1);
            *(float2*)(C + (size_t)r1 * N + c) = make_float2(v2, v3);
        }
    }
}

// ---------------- maxpool 3x3 s2 p1 : [B*C2,64,64] -> [B*C2,32,32] ----------------
__global__ __launch_bounds__(256) void maxpool_k(const float* __restrict__ in,
                                                 float* __restrict__ out) {
    int idx = blockIdx.x * blockDim.x + threadIdx.x;
    if (idx >= BSZ * C2 * 1024) return;
    int ow = idx & 31, oh = (idx >> 5) & 31, ch = idx >> 10;
    const float* p = in + (size_t)ch * 4096;
    int h0 = oh * 2 - 1, w0 = ow * 2 - 1;
    float m = -INFINITY;
#pragma unroll
    for (int dh = 0; dh < 3; dh++) {
        int h = h0 + dh;
        if (h < 0 || h >= 64) continue;
#pragma unroll
        for (int dw = 0; dw < 3; dw++) {
            int w = w0 + dw;
            if (w < 0 || w >= 64) continue;
            m = fmaxf(m, p[h * 64 + w]);
        }
    }
    out[idx] = m;
}

// ---------------- per-row max & sum(exp(x-max)) over 1024-wide rows ----------------
__global__ __launch_bounds__(256) void stats_k(const float* __restrict__ S,
                                               float* __restrict__ rmax,
                                               float* __restrict__ rsum) {
    int warp = (blockIdx.x * blockDim.x + threadIdx.x) >> 5;
    int lane = threadIdx.x & 31;
    if (warp >= BSZ * HW) return;
    const float* row = S + (size_t)warp * 1024;
    float v[32];
    float mx = -INFINITY;
#pragma unroll
    for (int i = 0; i < 32; i++) {
        v[i] = row[lane + i * 32];
        mx = fmaxf(mx, v[i]);
    }
#pragma unroll
    for (int o = 16; o > 0; o >>= 1)
        mx = fmaxf(mx, __shfl_xor_sync(0xffffffffu, mx, o));
    float s = 0.f;
#pragma unroll
    for (int i = 0; i < 32; i++) s += __expf(v[i] - mx);
#pragma unroll
    for (int o = 16; o > 0; o >>= 1)
        s += __shfl_xor_sync(0xffffffffu, s, o);
    if (lane == 0) {
        rmax[warp] = mx;
        rsum[warp] = s;
    }
}

// ---------------- launcher ----------------
extern "C" void kernel_launch(void* const* d_in, const int* in_sizes, int n_in,
                              void* d_out, int out_size) {
    const float* a       = (const float*)d_in[0];
    const float* conv1_w = (const float*)d_in[1];
    const float* conv1_b = (const float*)d_in[2];
    const float* bn1_g   = (const float*)d_in[3];
    const float* bn1_b   = (const float*)d_in[4];
    const float* bn1_m   = (const float*)d_in[5];
    const float* bn1_v   = (const float*)d_in[6];
    const float* conv2_w = (const float*)d_in[7];
    const float* conv2_b = (const float*)d_in[8];
    const float* bn2_g   = (const float*)d_in[9];
    const float* bn2_b   = (const float*)d_in[10];
    const float* bn2_m   = (const float*)d_in[11];
    const float* bn2_v   = (const float*)d_in[12];
    const float* conv3_w = (const float*)d_in[13];
    const float* conv3_b = (const float*)d_in[14];
    const float* bn3_g   = (const float*)d_in[15];
    const float* bn3_b   = (const float*)d_in[16];
    const float* bn3_m   = (const float*)d_in[17];
    const float* bn3_v   = (const float*)d_in[18];
    float* out = (float*)d_out;

    float *px1, *pc2, *pp, *pS, *prm, *prs, *pO;
    cudaGetSymbolAddress((void**)&px1, g_x1);
    cudaGetSymbolAddress((void**)&pc2, g_c2);
    cudaGetSymbolAddress((void**)&pp, g_p23);
    cudaGetSymbolAddress((void**)&pS, g_S);
    cudaGetSymbolAddress((void**)&prm, g_rmax);
    cudaGetSymbolAddress((void**)&prs, g_rsum);
    cudaGetSymbolAddress((void**)&pO, g_O);

    GemmArgs ga;

    // K1: x1 = ReLU(BN(conv1(a)))  ->  [B,128,4096] NCHW flat
    ga = {};
    ga.A = conv1_w; ga.B = a; ga.C = px1;
    ga.M = C2; ga.N = HW; ga.K = CIN;
    ga.sAb = 0; ga.sBb = (long long)CIN * HW; ga.sCb = (long long)C2 * HW;
    ga.bias = conv1_b; ga.g = bn1_g; ga.beta = bn1_b; ga.mean = bn1_m; ga.var = bn1_v;
    gemm_mma<1><<<dim3(HW / 128, C2 / 128, BSZ), 128>>>(ga);

    // K2: conv2 branch (pre-pool)
    ga = {};
    ga.A = conv2_w; ga.B = a; ga.C = pc2;
    ga.M = C2; ga.N = HW; ga.K = CIN;
    ga.sAb = 0; ga.sBb = (long long)CIN * HW; ga.sCb = (long long)C2 * HW;
    ga.bias = conv2_b; ga.g = bn2_g; ga.beta = bn2_b; ga.mean = bn2_m; ga.var = bn2_v;
    gemm_mma<1><<<dim3(HW / 128, C2 / 128, BSZ), 128>>>(ga);

    // K3: maxpool -> pooled (x2/x3 views)
    maxpool_k<<<(BSZ * C2 * 1024 + 255) / 256, 256>>>(pc2, pp);

    // K4: S = x1 @ x2   (M=4096, N=1024, K=128)
    ga = {};
    ga.A = px1; ga.B = pp; ga.C = pS;
    ga.M = HW; ga.N = HW4; ga.K = C2;
    ga.sAb = (long long)HW * C2; ga.sBb = (long long)C2 * HW4;
    ga.sCb = (long long)HW * HW4;
    gemm_mma<0><<<dim3(HW4 / 128, HW / 128, BSZ), 128>>>(ga);

    // K5: row softmax stats
    stats_k<<<(BSZ * HW) / 8, 256>>>(pS, prm, prs);

    // K6: O = softmax(S) @ x3   (M=4096, N=128, K=1024)
    ga = {};
    ga.A = pS; ga.B = pp; ga.C = pO;
    ga.M = HW; ga.N = C2; ga.K = HW4;
    ga.sAb = (long long)HW * HW4; ga.sBb = (long long)C2 * HW4;
    ga.sCb = (long long)HW * C2;
    ga.rowmax = prm; ga.rowsum = prs;
    gemm_mma<3><<<dim3(C2 / 128, HW / 128, BSZ), 128>>>(ga);

    // K7: out = ReLU(BN(conv3(O))) + a   (M=256, N=4096, K=128)
    ga = {};
    ga.A = conv3_w; ga.B = pO; ga.C = out;
    ga.M = CIN; ga.N = HW; ga.K = C2;
    ga.sAb = 0; ga.sBb = (long long)C2 * HW; ga.sCb = (long long)CIN * HW;
    ga.bias = conv3_b; ga.g = bn3_g; ga.beta = bn3_b; ga.mean = bn3_m; ga.var = bn3_v;
    ga.res = a; ga.sResB = (long long)CIN * HW;
    gemm_mma<2><<<dim3(HW / 128, CIN / 128, BSZ), 128>>>(ga);
}

// round 6
// speedup vs baseline: 2.5349x; 1.0495x over previous
#include <cuda_runtime.h>
#include <math.h>
#include <stdint.h>

#define EPSBN 1e-5f
#define BSZ 8
#define CIN 256
#define C2 128
#define HW 4096
#define HW4 1024

// ---------------- scratch (device globals; no runtime allocation) ----------------
__device__ float g_x1[(size_t)BSZ * HW * C2];      // conv1 out NCHW flat == x1 [4096,128] rm
__device__ float g_c2[(size_t)BSZ * C2 * HW];      // conv2 out (pre-pool) NCHW
__device__ float g_p23[(size_t)BSZ * C2 * HW4];    // pooled: x2 [128,1024] rm == x3 [1024,128] rm
__device__ float g_S[(size_t)BSZ * HW * HW4];      // logits [4096,1024] per batch
__device__ float g_rmax[BSZ * HW];
__device__ float g_rsum[BSZ * HW];
__device__ float g_O[(size_t)BSZ * HW * C2];       // attn out [4096,128] rm == NCHW [128,4096]

// ---------------- helpers ----------------
__device__ __forceinline__ uint32_t f2tf32(float f) {
    uint32_t u;
    asm("cvt.rna.tf32.f32 %0, %1;" : "=r"(u) : "f"(f));
    return u;
}

__device__ __forceinline__ void mma_tf32(float d[4], uint32_t a0, uint32_t a1,
                                         uint32_t a2, uint32_t a3,
                                         uint32_t b0, uint32_t b1) {
    asm volatile(
        "mma.sync.aligned.m16n8k8.row.col.f32.tf32.tf32.f32 "
        "{%0,%1,%2,%3},{%4,%5,%6,%7},{%8,%9},{%0,%1,%2,%3};"
        : "+f"(d[0]), "+f"(d[1]), "+f"(d[2]), "+f"(d[3])
        : "r"(a0), "r"(a1), "r"(a2), "r"(a3), "r"(b0), "r"(b1));
}

// ---------------- tensor-core tiled GEMM: C = f(A[M,K] rm) * B[K,N] rm ----------
// 128x128 CTA tile, 4 warps of 64x64, double-buffered smem.
// A kept ROW-MAJOR in smem (pad 20) -> STS.128 stores, conflict-free frag reads.
// MODE 0: plain store
// MODE 1: BN+ReLU epilogue (per-M-row channel params)
// MODE 2: BN+ReLU + residual add
// MODE 3: A-transform exp(a - rowmax[m]); epilogue scale by 1/rowsum[m]
struct GemmArgs {
    const float* A; const float* B; float* C;
    int M, N, K;
    long long sAb, sBb, sCb;
    const float* bias; const float* g; const float* beta;
    const float* mean; const float* var;
    const float* res; long long sResB;
    const float* rowmax; const float* rowsum;
};

#define APAD 20   // A row stride (words): (gp*20+lq)%32 hits 32 distinct banks
#define SMS 136   // B row stride (words): (lq*136+gp)%32 hits 32 distinct banks

template <int MODE>
__global__ __launch_bounds__(128) void gemm_mma(GemmArgs ga) {
    __shared__ uint32_t As[2][128][APAD];  // [buf][m][k] row-major, tf32 bits
    __shared__ uint32_t Bs[2][16][SMS];    // [buf][k][n], tf32 bits

    const int bz = blockIdx.z;
    const float* A = ga.A + (size_t)bz * ga.sAb;
    const float* Bp = ga.B + (size_t)bz * ga.sBb;
    float* C = ga.C + (size_t)bz * ga.sCb;

    const int mBase = blockIdx.y * 128;
    const int nBase = blockIdx.x * 128;
    const int tid = threadIdx.x;
    const int lane = tid & 31;
    const int warp = tid >> 5;         // 0..3
    const int wm = warp >> 1;          // 0..1 (64 rows)
    const int wn = warp & 1;           // 0..1 (64 cols)
    const int gp = lane >> 2;          // 0..7
    const int lq = lane & 3;           // 0..3
    const int N = ga.N, K = ga.K;

    // loader assignments: 4 float4 each for A and B per 16-k chunk (128 threads)
    int aRow[4], aK4[4], bKr[4], bN4[4];
#pragma unroll
    for (int it = 0; it < 4; it++) {
        int idx = tid + it * 128;
        aRow[it] = idx >> 2;
        aK4[it] = (idx & 3) << 2;
        bKr[it] = idx >> 5;
        bN4[it] = (idx & 31) << 2;
    }

    float rmA[4] = {0.f, 0.f, 0.f, 0.f};
    if (MODE == 3) {
        const float* rmax = ga.rowmax + (size_t)bz * ga.M;
#pragma unroll
        for (int it = 0; it < 4; it++) rmA[it] = rmax[mBase + aRow[it]];
    }

    float acc[4][8][4];
#pragma unroll
    for (int i = 0; i < 4; i++)
#pragma unroll
        for (int j = 0; j < 8; j++)
#pragma unroll
            for (int r = 0; r < 4; r++) acc[i][j][r] = 0.f;

    float4 ra[4], rb[4];

    // prologue: load chunk 0 into regs
#pragma unroll
    for (int it = 0; it < 4; it++) {
        ra[it] = *(const float4*)(A + (size_t)(mBase + aRow[it]) * K + aK4[it]);
        rb[it] = *(const float4*)(Bp + (size_t)bKr[it] * N + nBase + bN4[it]);
    }

    int buf = 0;
    for (int k0 = 0; k0 < K; k0 += 16) {
        // regs -> smem[buf]  (A row-major STS.128; B transposed rows are natural)
#pragma unroll
        for (int it = 0; it < 4; it++) {
            float v[4] = {ra[it].x, ra[it].y, ra[it].z, ra[it].w};
            if (MODE == 3) {
#pragma unroll
                for (int c = 0; c < 4; c++) v[c] = __expf(v[c] - rmA[it]);
            }
            uint4 ua;
            ua.x = f2tf32(v[0]); ua.y = f2tf32(v[1]);
            ua.z = f2tf32(v[2]); ua.w = f2tf32(v[3]);
            *(uint4*)&As[buf][aRow[it]][aK4[it]] = ua;

            uint4 ub;
            ub.x = f2tf32(rb[it].x); ub.y = f2tf32(rb[it].y);
            ub.z = f2tf32(rb[it].z); ub.w = f2tf32(rb[it].w);
            *(uint4*)&Bs[buf][bKr[it]][bN4[it]] = ub;
        }
        __syncthreads();

        // prefetch next chunk into regs
        if (k0 + 16 < K) {
#pragma unroll
            for (int it = 0; it < 4; it++) {
                ra[it] = *(const float4*)(A + (size_t)(mBase + aRow[it]) * K +
                                          (k0 + 16) + aK4[it]);
                rb[it] = *(const float4*)(Bp + (size_t)(k0 + 16 + bKr[it]) * N +
                                          nBase + bN4[it]);
            }
        }

        // compute on smem[buf]: 64x64 warp tile
#pragma unroll
        for (int ks8 = 0; ks8 < 2; ks8++) {
            const int kb = ks8 * 8;
            uint32_t b0[8], b1[8];
#pragma unroll
            for (int j = 0; j < 8; j++) {
                int n = wn * 64 + j * 8 + gp;
                b0[j] = Bs[buf][kb + lq][n];
                b1[j] = Bs[buf][kb + lq + 4][n];
            }
#pragma unroll
            for (int i = 0; i < 4; i++) {
                int m0 = wm * 64 + i * 16 + gp;
                uint32_t a0 = As[buf][m0][kb + lq];
                uint32_t a1 = As[buf][m0 + 8][kb + lq];
                uint32_t a2 = As[buf][m0][kb + lq + 4];
                uint32_t a3 = As[buf][m0 + 8][kb + lq + 4];
#pragma unroll
                for (int j = 0; j < 8; j++)
                    mma_tf32(acc[i][j], a0, a1, a2, a3, b0[j], b1[j]);
            }
        }
        buf ^= 1;
    }

    // epilogue: rows r0 = mBase+wm*64+i*16+gp, r1 = r0+8
#pragma unroll
    for (int i = 0; i < 4; i++) {
        int r0 = mBase + wm * 64 + i * 16 + gp;
        int r1 = r0 + 8;
        float sc0 = 1.f, sh0 = 0.f, bi0 = 0.f, iv0 = 1.f;
        float sc1 = 1.f, sh1 = 0.f, bi1 = 0.f, iv1 = 1.f;
        if (MODE == 1 || MODE == 2) {
            sc0 = ga.g[r0] * rsqrtf(ga.var[r0] + EPSBN);
            sh0 = ga.beta[r0] - ga.mean[r0] * sc0;
            bi0 = ga.bias[r0];
            sc1 = ga.g[r1] * rsqrtf(ga.var[r1] + EPSBN);
            sh1 = ga.beta[r1] - ga.mean[r1] * sc1;
            bi1 = ga.bias[r1];
        }
        if (MODE == 3) {
            iv0 = 1.0f / ga.rowsum[(size_t)bz * ga.M + r0];
            iv1 = 1.0f / ga.rowsum[(size_t)bz * ga.M + r1];
        }
#pragma unroll
        for (int j = 0; j < 8; j++) {
            int c = nBase + wn * 64 + j * 8 + 2 * lq;
            float v0 = acc[i][j][0], v1 = acc[i][j][1];
            float v2 = acc[i][j][2], v3 = acc[i][j][3];
            if (MODE == 1 || MODE == 2) {
                v0 = fmaxf((v0 + bi0) * sc0 + sh0, 0.f);
                v1 = fmaxf((v1 + bi0) * sc0 + sh0, 0.f);
                v2 = fmaxf((v2 + bi1) * sc1 + sh1, 0.f);
                v3 = fmaxf((v3 + bi1) * sc1 + sh1, 0.f);
            }
            if (MODE == 2) {
                const float* rp = ga.res + (size_t)bz * ga.sResB;
                float2 q0 = *(const float2*)(rp + (size_t)r0 * N + c);
                float2 q1 = *(const float2*)(rp + (size_t)r1 * N + c);
                v0 += q0.x; v1 += q0.y; v2 += q1.x; v3 += q1.y;
            }
            if (MODE == 3) { v0 *= iv0; v1 *= iv0; v2 *= iv1; v3 *= iv1; }
            *(float2*)(C + (size_t)r0 * N + c) = make_float2(v0, v1);
            *(float2*)(C + (size_t)r1 * N + c) = make_float2(v2, v3);
        }
    }
}

// ---------------- maxpool 3x3 s2 p1 : [B*C2,64,64] -> [B*C2,32,32] ----------------
__global__ __launch_bounds__(256) void maxpool_k(const float* __restrict__ in,
                                                 float* __restrict__ out) {
    int idx = blockIdx.x * blockDim.x + threadIdx.x;
    if (idx >= BSZ * C2 * 1024) return;
    int ow = idx & 31, oh = (idx >> 5) & 31, ch = idx >> 10;
    const float* p = in + (size_t)ch * 4096;
    int h0 = oh * 2 - 1, w0 = ow * 2 - 1;
    float m = -INFINITY;
#pragma unroll
    for (int dh = 0; dh < 3; dh++) {
        int h = h0 + dh;
        if (h < 0 || h >= 64) continue;
#pragma unroll
        for (int dw = 0; dw < 3; dw++) {
            int w = w0 + dw;
            if (w < 0 || w >= 64) continue;
            m = fmaxf(m, p[h * 64 + w]);
        }
    }
    out[idx] = m;
}

// ---------------- per-row max & sum(exp(x-max)) over 1024-wide rows ----------------
__global__ __launch_bounds__(256) void stats_k(const float* __restrict__ S,
                                               float* __restrict__ rmax,
                                               float* __restrict__ rsum) {
    int warp = (blockIdx.x * blockDim.x + threadIdx.x) >> 5;
    int lane = threadIdx.x & 31;
    if (warp >= BSZ * HW) return;
    const float* row = S + (size_t)warp * 1024;
    float v[32];
    float mx = -INFINITY;
#pragma unroll
    for (int i = 0; i < 32; i++) {
        v[i] = row[lane + i * 32];
        mx = fmaxf(mx, v[i]);
    }
#pragma unroll
    for (int o = 16; o > 0; o >>= 1)
        mx = fmaxf(mx, __shfl_xor_sync(0xffffffffu, mx, o));
    float s = 0.f;
#pragma unroll
    for (int i = 0; i < 32; i++) s += __expf(v[i] - mx);
#pragma unroll
    for (int o = 16; o > 0; o >>= 1)
        s += __shfl_xor_sync(0xffffffffu, s, o);
    if (lane == 0) {
        rmax[warp] = mx;
        rsum[warp] = s;
    }
}

// ---------------- launcher ----------------
extern "C" void kernel_launch(void* const* d_in, const int* in_sizes, int n_in,
                              void* d_out, int out_size) {
    const float* a       = (const float*)d_in[0];
    const float* conv1_w = (const float*)d_in[1];
    const float* conv1_b = (const float*)d_in[2];
    const float* bn1_g   = (const float*)d_in[3];
    const float* bn1_b   = (const float*)d_in[4];
    const float* bn1_m   = (const float*)d_in[5];
    const float* bn1_v   = (const float*)d_in[6];
    const float* conv2_w = (const float*)d_in[7];
    const float* conv2_b = (const float*)d_in[8];
    const float* bn2_g   = (const float*)d_in[9];
    const float* bn2_b   = (const float*)d_in[10];
    const float* bn2_m   = (const float*)d_in[11];
    const float* bn2_v   = (const float*)d_in[12];
    const float* conv3_w = (const float*)d_in[13];
    const float* conv3_b = (const float*)d_in[14];
    const float* bn3_g   = (const float*)d_in[15];
    const float* bn3_b   = (const float*)d_in[16];
    const float* bn3_m   = (const float*)d_in[17];
    const float* bn3_v   = (const float*)d_in[18];
    float* out = (float*)d_out;

    float *px1, *pc2, *pp, *pS, *prm, *prs, *pO;
    cudaGetSymbolAddress((void**)&px1, g_x1);
    cudaGetSymbolAddress((void**)&pc2, g_c2);
    cudaGetSymbolAddress((void**)&pp, g_p23);
    cudaGetSymbolAddress((void**)&pS, g_S);
    cudaGetSymbolAddress((void**)&prm, g_rmax);
    cudaGetSymbolAddress((void**)&prs, g_rsum);
    cudaGetSymbolAddress((void**)&pO, g_O);

    GemmArgs ga;

    // K1: x1 = ReLU(BN(conv1(a)))  ->  [B,128,4096] NCHW flat
    ga = {};
    ga.A = conv1_w; ga.B = a; ga.C = px1;
    ga.M = C2; ga.N = HW; ga.K = CIN;
    ga.sAb = 0; ga.sBb = (long long)CIN * HW; ga.sCb = (long long)C2 * HW;
    ga.bias = conv1_b; ga.g = bn1_g; ga.beta = bn1_b; ga.mean = bn1_m; ga.var = bn1_v;
    gemm_mma<1><<<dim3(HW / 128, C2 / 128, BSZ), 128>>>(ga);

    // K2: conv2 branch (pre-pool)
    ga = {};
    ga.A = conv2_w; ga.B = a; ga.C = pc2;
    ga.M = C2; ga.N = HW; ga.K = CIN;
    ga.sAb = 0; ga.sBb = (long long)CIN * HW; ga.sCb = (long long)C2 * HW;
    ga.bias = conv2_b; ga.g = bn2_g; ga.beta = bn2_b; ga.mean = bn2_m; ga.var = bn2_v;
    gemm_mma<1><<<dim3(HW / 128, C2 / 128, BSZ), 128>>>(ga);

    // K3: maxpool -> pooled (x2/x3 views)
    maxpool_k<<<(BSZ * C2 * 1024 + 255) / 256, 256>>>(pc2, pp);

    // K4: S = x1 @ x2   (M=4096, N=1024, K=128)
    ga = {};
    ga.A = px1; ga.B = pp; ga.C = pS;
    ga.M = HW; ga.N = HW4; ga.K = C2;
    ga.sAb = (long long)HW * C2; ga.sBb = (long long)C2 * HW4;
    ga.sCb = (long long)HW * HW4;
    gemm_mma<0><<<dim3(HW4 / 128, HW / 128, BSZ), 128>>>(ga);

    // K5: row softmax stats
    stats_k<<<(BSZ * HW) / 8, 256>>>(pS, prm, prs);

    // K6: O = softmax(S) @ x3   (M=4096, N=128, K=1024)
    ga = {};
    ga.A = pS; ga.B = pp; ga.C = pO;
    ga.M = HW; ga.N = C2; ga.K = HW4;
    ga.sAb = (long long)HW * HW4; ga.sBb = (long long)C2 * HW4;
    ga.sCb = (long long)HW * C2;
    ga.rowmax = prm; ga.rowsum = prs;
    gemm_mma<3><<<dim3(C2 / 128, HW / 128, BSZ), 128>>>(ga);

    // K7: out = ReLU(BN(conv3(O))) + a   (M=256, N=4096, K=128)
    ga = {};
    ga.A = conv3_w; ga.B = pO; ga.C = out;
    ga.M = CIN; ga.N = HW; ga.K = C2;
    ga.sAb = 0; ga.sBb = (long long)C2 * HW; ga.sCb = (long long)CIN * HW;
    ga.bias = conv3_b; ga.g = bn3_g; ga.beta = bn3_b; ga.mean = bn3_m; ga.var = bn3_v;
    ga.res = a; ga.sResB = (long long)CIN * HW;
    gemm_mma<2><<<dim3(HW / 128, CIN / 128, BSZ), 128>>>(ga);
}

// round 12
// speedup vs baseline: 3.0398x; 1.1992x over previous
#include <cuda_runtime.h>
#include <cuda_fp16.h>
#include <math.h>
#include <stdint.h>

#define EPSBN 1e-5f
#define BSZ 8
#define CIN 256
#define C2 128
#define HW 4096
#define HW4 1024

// ---------------- scratch (device globals; no runtime allocation) ----------------
__device__ float g_x1[(size_t)BSZ * HW * C2];      // conv1 out NCHW flat == x1 [4096,128] rm
__device__ float g_c2[(size_t)BSZ * C2 * HW];      // conv2 out (pre-pool) NCHW
__device__ float g_p23[(size_t)BSZ * C2 * HW4];    // pooled: x2 [128,1024] rm == x3 [1024,128] rm
__device__ float g_S[(size_t)BSZ * HW * HW4];      // logits [4096,1024] per batch
__device__ float g_rmax[BSZ * HW];
__device__ float g_rsum[BSZ * HW];
__device__ float g_O[(size_t)BSZ * HW * C2];       // attn out [4096,128] rm == NCHW [128,4096]

// ---------------- helpers ----------------
__device__ __forceinline__ uint32_t f2h2(float lo, float hi) {
    __half2 h = __floats2half2_rn(lo, hi);
    return *(uint32_t*)&h;
}

__device__ __forceinline__ void mma_f16(float d[4], uint32_t a0, uint32_t a1,
                                        uint32_t a2, uint32_t a3,
                                        uint32_t b0, uint32_t b1) {
    asm volatile(
        "mma.sync.aligned.m16n8k16.row.col.f32.f16.f16.f32 "
        "{%0,%1,%2,%3},{%4,%5,%6,%7},{%8,%9},{%0,%1,%2,%3};"
        : "+f"(d[0]), "+f"(d[1]), "+f"(d[2]), "+f"(d[3])
        : "r"(a0), "r"(a1), "r"(a2), "r"(a3), "r"(b0), "r"(b1));
}

// ---------------- fp16 tensor-core tiled GEMM: C = f(A[M,K] rm) * B[K,N] rm -------
// 128x128 CTA tile, 4 warps of 64x64, double-buffered smem, K-chunk 16.
// A smem: [m][k-halfpair] row-major (8 uint32/row + pad to 12).
// B smem: [kpair][n] half2 = (B[2kp][n], B[2kp+1][n]) (SMS=136 pad).
// MODE 0: plain store
// MODE 1: BN+ReLU epilogue (per-M-row channel params)
// MODE 2: BN+ReLU + residual add
// MODE 3: A-transform exp(a - rowmax[m]); epilogue scale by 1/rowsum[m]
struct GemmArgs {
    const float* A; const float* B; float* C;
    int M, N, K;
    long long sAb, sBb, sCb;
    const float* bias; const float* g; const float* beta;
    const float* mean; const float* var;
    const float* res; long long sResB;
    const float* rowmax; const float* rowsum;
};

#define APAD 12   // uint32 row stride for A: (gp*12+lq)%32 distinct -> conflict-free
#define SMS 136   // uint32 row stride for B: (lq*136+gp)%32 distinct -> conflict-free

template <int MODE>
__global__ __launch_bounds__(128) void gemm_mma(GemmArgs ga) {
    __shared__ uint32_t As[2][128][APAD];  // [buf][m][kp] fp16x2
    __shared__ uint32_t Bs[2][8][SMS];     // [buf][kp][n] fp16x2 (k even/odd packed)

    const int bz = blockIdx.z;
    const float* A = ga.A + (size_t)bz * ga.sAb;
    const float* Bp = ga.B + (size_t)bz * ga.sBb;
    float* C = ga.C + (size_t)bz * ga.sCb;

    const int mBase = blockIdx.y * 128;
    const int nBase = blockIdx.x * 128;
    const int tid = threadIdx.x;
    const int lane = tid & 31;
    const int warp = tid >> 5;         // 0..3
    const int wm = warp >> 1;          // 0..1 (64 rows)
    const int wn = warp & 1;           // 0..1 (64 cols)
    const int gp = lane >> 2;          // 0..7
    const int lq = lane & 3;           // 0..3
    const int N = ga.N, K = ga.K;

    // A loader: 4 float4 per chunk (rows 0..127, k4 in {0,4,8,12})
    // B loader: 2 pair-loads per chunk: (kp 0..7, n4), rows 2kp & 2kp+1
    int aRow[4], aK4[4], bKp[2], bN4[2];
#pragma unroll
    for (int it = 0; it < 4; it++) {
        int idx = tid + it * 128;
        aRow[it] = idx >> 2;
        aK4[it] = (idx & 3) << 2;
    }
#pragma unroll
    for (int it = 0; it < 2; it++) {
        int idx = tid + it * 128;
        bKp[it] = idx >> 5;            // 0..7
        bN4[it] = (idx & 31) << 2;     // 0..124
    }

    float rmA[4] = {0.f, 0.f, 0.f, 0.f};
    if (MODE == 3) {
        const float* rmax = ga.rowmax + (size_t)bz * ga.M;
#pragma unroll
        for (int it = 0; it < 4; it++) rmA[it] = rmax[mBase + aRow[it]];
    }

    float acc[4][8][4];
#pragma unroll
    for (int i = 0; i < 4; i++)
#pragma unroll
        for (int j = 0; j < 8; j++)
#pragma unroll
            for (int r = 0; r < 4; r++) acc[i][j][r] = 0.f;

    float4 ra[4], rb0[2], rb1[2];

    // prologue: load chunk 0
#pragma unroll
    for (int it = 0; it < 4; it++)
        ra[it] = *(const float4*)(A + (size_t)(mBase + aRow[it]) * K + aK4[it]);
#pragma unroll
    for (int it = 0; it < 2; it++) {
        rb0[it] = *(const float4*)(Bp + (size_t)(2 * bKp[it]) * N + nBase + bN4[it]);
        rb1[it] = *(const float4*)(Bp + (size_t)(2 * bKp[it] + 1) * N + nBase + bN4[it]);
    }

    int buf = 0;
    for (int k0 = 0; k0 < K; k0 += 16) {
        // regs -> smem[buf] with fp16 conversion
#pragma unroll
        for (int it = 0; it < 4; it++) {
            float v[4] = {ra[it].x, ra[it].y, ra[it].z, ra[it].w};
            if (MODE == 3) {
#pragma unroll
                for (int c = 0; c < 4; c++) v[c] = __expf(v[c] - rmA[it]);
            }
            uint2 ua;
            ua.x = f2h2(v[0], v[1]);
            ua.y = f2h2(v[2], v[3]);
            *(uint2*)&As[buf][aRow[it]][aK4[it] >> 1] = ua;
        }
#pragma unroll
        for (int it = 0; it < 2; it++) {
            uint4 ub;
            ub.x = f2h2(rb0[it].x, rb1[it].x);
            ub.y = f2h2(rb0[it].y, rb1[it].y);
            ub.z = f2h2(rb0[it].z, rb1[it].z);
            ub.w = f2h2(rb0[it].w, rb1[it].w);
            *(uint4*)&Bs[buf][bKp[it]][bN4[it]] = ub;
        }
        __syncthreads();

        // prefetch next chunk
        if (k0 + 16 < K) {
#pragma unroll
            for (int it = 0; it < 4; it++)
                ra[it] = *(const float4*)(A + (size_t)(mBase + aRow[it]) * K +
                                          (k0 + 16) + aK4[it]);
#pragma unroll
            for (int it = 0; it < 2; it++) {
                rb0[it] = *(const float4*)(Bp + (size_t)(k0 + 16 + 2 * bKp[it]) * N +
                                           nBase + bN4[it]);
                rb1[it] = *(const float4*)(Bp + (size_t)(k0 + 17 + 2 * bKp[it]) * N +
                                           nBase + bN4[it]);
            }
        }

        // compute: one m16n8k16 k-step covers the whole 16-k chunk
        {
            uint32_t b0[8], b1[8];
#pragma unroll
            for (int j = 0; j < 8; j++) {
                int n = wn * 64 + j * 8 + gp;
                b0[j] = Bs[buf][lq][n];
                b1[j] = Bs[buf][lq + 4][n];
            }
#pragma unroll
            for (int i = 0; i < 4; i++) {
                int m0 = wm * 64 + i * 16 + gp;
                uint32_t a0 = As[buf][m0][lq];
                uint32_t a1 = As[buf][m0 + 8][lq];
                uint32_t a2 = As[buf][m0][lq + 4];
                uint32_t a3 = As[buf][m0 + 8][lq + 4];
#pragma unroll
                for (int j = 0; j < 8; j++)
                    mma_f16(acc[i][j], a0, a1, a2, a3, b0[j], b1[j]);
            }
        }
        buf ^= 1;
    }

    // epilogue: rows r0 = mBase+wm*64+i*16+gp, r1 = r0+8
#pragma unroll
    for (int i = 0; i < 4; i++) {
        int r0 = mBase + wm * 64 + i * 16 + gp;
        int r1 = r0 + 8;
        float sc0 = 1.f, sh0 = 0.f, bi0 = 0.f, iv0 = 1.f;
        float sc1 = 1.f, sh1 = 0.f, bi1 = 0.f, iv1 = 1.f;
        if (MODE == 1 || MODE == 2) {
            sc0 = ga.g[r0] * rsqrtf(ga.var[r0] + EPSBN);
            sh0 = ga.beta[r0] - ga.mean[r0] * sc0;
            bi0 = ga.bias[r0];
            sc1 = ga.g[r1] * rsqrtf(ga.var[r1] + EPSBN);
            sh1 = ga.beta[r1] - ga.mean[r1] * sc1;
            bi1 = ga.bias[r1];
        }
        if (MODE == 3) {
            iv0 = 1.0f / ga.rowsum[(size_t)bz * ga.M + r0];
            iv1 = 1.0f / ga.rowsum[(size_t)bz * ga.M + r1];
        }
#pragma unroll
        for (int j = 0; j < 8; j++) {
            int c = nBase + wn * 64 + j * 8 + 2 * lq;
            float v0 = acc[i][j][0], v1 = acc[i][j][1];
            float v2 = acc[i][j][2], v3 = acc[i][j][3];
            if (MODE == 1 || MODE == 2) {
                v0 = fmaxf((v0 + bi0) * sc0 + sh0, 0.f);
                v1 = fmaxf((v1 + bi0) * sc0 + sh0, 0.f);
                v2 = fmaxf((v2 + bi1) * sc1 + sh1, 0.f);
                v3 = fmaxf((v3 + bi1) * sc1 + sh1, 0.f);
            }
            if (MODE == 2) {
                const float* rp = ga.res + (size_t)bz * ga.sResB;
                float2 q0 = *(const float2*)(rp + (size_t)r0 * N + c);
                float2 q1 = *(const float2*)(rp + (size_t)r1 * N + c);
                v0 += q0.x; v1 += q0.y; v2 += q1.x; v3 += q1.y;
            }
            if (MODE == 3) { v0 *= iv0; v1 *= iv0; v2 *= iv1; v3 *= iv1; }
            *(float2*)(C + (size_t)r0 * N + c) = make_float2(v0, v1);
            *(float2*)(C + (size_t)r1 * N + c) = make_float2(v2, v3);
        }
    }
}

// ---------------- maxpool 3x3 s2 p1 : [B*C2,64,64] -> [B*C2,32,32] ----------------
__global__ __launch_bounds__(256) void maxpool_k(const float* __restrict__ in,
                                                 float* __restrict__ out) {
    int idx = blockIdx.x * blockDim.x + threadIdx.x;
    if (idx >= BSZ * C2 * 1024) return;
    int ow = idx & 31, oh = (idx >> 5) & 31, ch = idx >> 10;
    const float* p = in + (size_t)ch * 4096;
    int h0 = oh * 2 - 1, w0 = ow * 2 - 1;
    float m = -INFINITY;
#pragma unroll
    for (int dh = 0; dh < 3; dh++) {
        int h = h0 + dh;
        if (h < 0 || h >= 64) continue;
#pragma unroll
        for (int dw = 0; dw < 3; dw++) {
            int w = w0 + dw;
            if (w < 0 || w >= 64) continue;
            m = fmaxf(m, p[h * 64 + w]);
        }
    }
    out[idx] = m;
}

// ---------------- per-row max & sum(exp(x-max)) over 1024-wide rows ----------------
__global__ __launch_bounds__(256) void stats_k(const float* __restrict__ S,
                                               float* __restrict__ rmax,
                                               float* __restrict__ rsum) {
    int warp = (blockIdx.x * blockDim.x + threadIdx.x) >> 5;
    int lane = threadIdx.x & 31;
    if (warp >= BSZ * HW) return;
    const float* row = S + (size_t)warp * 1024;
    float v[32];
    float mx = -INFINITY;
#pragma unroll
    for (int i = 0; i < 32; i++) {
        v[i] = row[lane + i * 32];
        mx = fmaxf(mx, v[i]);
    }
#pragma unroll
    for (int o = 16; o > 0; o >>= 1)
        mx = fmaxf(mx, __shfl_xor_sync(0xffffffffu, mx, o));
    float s = 0.f;
#pragma unroll
    for (int i = 0; i < 32; i++) s += __expf(v[i] - mx);
#pragma unroll
    for (int o = 16; o > 0; o >>= 1)
        s += __shfl_xor_sync(0xffffffffu, s, o);
    if (lane == 0) {
        rmax[warp] = mx;
        rsum[warp] = s;
    }
}

// ---------------- launcher ----------------
extern "C" void kernel_launch(void* const* d_in, const int* in_sizes, int n_in,
                              void* d_out, int out_size) {
    const float* a       = (const float*)d_in[0];
    const float* conv1_w = (const float*)d_in[1];
    const float* conv1_b = (const float*)d_in[2];
    const float* bn1_g   = (const float*)d_in[3];
    const float* bn1_b   = (const float*)d_in[4];
    const float* bn1_m   = (const float*)d_in[5];
    const float* bn1_v   = (const float*)d_in[6];
    const float* conv2_w = (const float*)d_in[7];
    const float* conv2_b = (const float*)d_in[8];
    const float* bn2_g   = (const float*)d_in[9];
    const float* bn2_b   = (const float*)d_in[10];
    const float* bn2_m   = (const float*)d_in[11];
    const float* bn2_v   = (const float*)d_in[12];
    const float* conv3_w = (const float*)d_in[13];
    const float* conv3_b = (const float*)d_in[14];
    const float* bn3_g   = (const float*)d_in[15];
    const float* bn3_b   = (const float*)d_in[16];
    const float* bn3_m   = (const float*)d_in[17];
    const float* bn3_v   = (const float*)d_in[18];
    float* out = (float*)d_out;

    float *px1, *pc2, *pp, *pS, *prm, *prs, *pO;
    cudaGetSymbolAddress((void**)&px1, g_x1);
    cudaGetSymbolAddress((void**)&pc2, g_c2);
    cudaGetSymbolAddress((void**)&pp, g_p23);
    cudaGetSymbolAddress((void**)&pS, g_S);
    cudaGetSymbolAddress((void**)&prm, g_rmax);
    cudaGetSymbolAddress((void**)&prs, g_rsum);
    cudaGetSymbolAddress((void**)&pO, g_O);

    GemmArgs ga;

    // K1: x1 = ReLU(BN(conv1(a)))  ->  [B,128,4096] NCHW flat
    ga = {};
    ga.A = conv1_w; ga.B = a; ga.C = px1;
    ga.M = C2; ga.N = HW; ga.K = CIN;
    ga.sAb = 0; ga.sBb = (long long)CIN * HW; ga.sCb = (long long)C2 * HW;
    ga.bias = conv1_b; ga.g = bn1_g; ga.beta = bn1_b; ga.mean = bn1_m; ga.var = bn1_v;
    gemm_mma<1><<<dim3(HW / 128, C2 / 128, BSZ), 128>>>(ga);

    // K2: conv2 branch (pre-pool)
    ga = {};
    ga.A = conv2_w; ga.B = a; ga.C = pc2;
    ga.M = C2; ga.N = HW; ga.K = CIN;
    ga.sAb = 0; ga.sBb = (long long)CIN * HW; ga.sCb = (long long)C2 * HW;
    ga.bias = conv2_b; ga.g = bn2_g; ga.beta = bn2_b; ga.mean = bn2_m; ga.var = bn2_v;
    gemm_mma<1><<<dim3(HW / 128, C2 / 128, BSZ), 128>>>(ga);

    // K3: maxpool -> pooled (x2/x3 views)
    maxpool_k<<<(BSZ * C2 * 1024 + 255) / 256, 256>>>(pc2, pp);

    // K4: S = x1 @ x2   (M=4096, N=1024, K=128)
    ga = {};
    ga.A = px1; ga.B = pp; ga.C = pS;
    ga.M = HW; ga.N = HW4; ga.K = C2;
    ga.sAb = (long long)HW * C2; ga.sBb = (long long)C2 * HW4;
    ga.sCb = (long long)HW * HW4;
    gemm_mma<0><<<dim3(HW4 / 128, HW / 128, BSZ), 128>>>(ga);

    // K5: row softmax stats
    stats_k<<<(BSZ * HW) / 8, 256>>>(pS, prm, prs);

    // K6: O = softmax(S) @ x3   (M=4096, N=128, K=1024)
    ga = {};
    ga.A = pS; ga.B = pp; ga.C = pO;
    ga.M = HW; ga.N = C2; ga.K = HW4;
    ga.sAb = (long long)HW * HW4; ga.sBb = (long long)C2 * HW4;
    ga.sCb = (long long)HW * C2;
    ga.rowmax = prm; ga.rowsum = prs;
    gemm_mma<3><<<dim3(C2 / 128, HW / 128, BSZ), 128>>>(ga);

    // K7: out = ReLU(BN(conv3(O))) + a   (M=256, N=4096, K=128)
    ga = {};
    ga.A = conv3_w; ga.B = pO; ga.C = out;
    ga.M = CIN; ga.N = HW; ga.K = C2;
    ga.sAb = 0; ga.sBb = (long long)C2 * HW; ga.sCb = (long long)CIN * HW;
    ga.bias = conv3_b; ga.g = bn3_g; ga.beta = bn3_b; ga.mean = bn3_m; ga.var = bn3_v;
    ga.res = a; ga.sResB = (long long)CIN * HW;
    gemm_mma<2><<<dim3(HW / 128, CIN / 128, BSZ), 128>>>(ga);
}